// round 5
// baseline (speedup 1.0000x reference)
#include <cuda_runtime.h>
#include <cuda_bf16.h>
#include <math.h>
#include <stdint.h>

// Problem constants (dataset-fixed shapes)
#define B_SZ   1024
#define N_SZ   8192
#define M_C    3000        // N_COMMON
#define MP     3008        // padded M (multiple of 32, zero-filled tail)
#define EPS_B  1e-8f
#define CH     12          // common-grid points per thread (256*12=3072 >= MP)

// ---------------- scratch (no runtime allocation allowed) ----------------
__device__ __align__(16) __nv_bfloat16 g_y1c[B_SZ * MP];
__device__ __align__(16) __nv_bfloat16 g_y2c[B_SZ * MP];
__device__ float g_sq1[B_SZ];
__device__ float g_sq2[B_SZ];
__device__ float g_xmin;
__device__ float g_xmax;

// ---------------- kernel 1: batch-scalar min/max ----------------
__global__ void minmax_kernel(const float* __restrict__ x, int B, int N) {
    __shared__ float smin[32], smax[32];
    int tid = threadIdx.x;
    float mn = INFINITY, mx = -INFINITY;
    for (int b = tid; b < B; b += blockDim.x) {
        mn = fminf(mn, x[(size_t)b * N]);
        mx = fmaxf(mx, x[(size_t)b * N + (N - 1)]);
    }
    #pragma unroll
    for (int o = 16; o > 0; o >>= 1) {
        mn = fminf(mn, __shfl_xor_sync(0xffffffffu, mn, o));
        mx = fmaxf(mx, __shfl_xor_sync(0xffffffffu, mx, o));
    }
    if ((tid & 31) == 0) { smin[tid >> 5] = mn; smax[tid >> 5] = mx; }
    __syncthreads();
    if (tid < 32) {
        int nw = (blockDim.x + 31) >> 5;
        mn = (tid < nw) ? smin[tid] : INFINITY;
        mx = (tid < nw) ? smax[tid] : -INFINITY;
        #pragma unroll
        for (int o = 16; o > 0; o >>= 1) {
            mn = fminf(mn, __shfl_xor_sync(0xffffffffu, mn, o));
            mx = fmaxf(mx, __shfl_xor_sync(0xffffffffu, mx, o));
        }
        if (tid == 0) { g_xmin = mn; g_xmax = mx; }
    }
}

// ---------------- kernel 2: interpolation (chunked incremental search) -----
// One block per batch row; x row in shared. Each thread owns CH consecutive
// common-grid points: ONE binary search for the first, then monotone linear
// advance of the lower_bound index for the rest (xc increasing in m).
// Produces the exact same lo as a fresh lower_bound per point.
__global__ __launch_bounds__(256) void interp_kernel(
    const float* __restrict__ x,
    const float* __restrict__ y1,
    const float* __restrict__ y2,
    int N)
{
    __shared__ float sx[N_SZ];
    __shared__ float red1[8], red2[8];

    const int b   = blockIdx.x;
    const int tid = threadIdx.x;

    const float* xr  = x  + (size_t)b * N;
    const float* y1r = y1 + (size_t)b * N;
    const float* y2r = y2 + (size_t)b * N;
    __nv_bfloat16* o1 = g_y1c + (size_t)b * MP;
    __nv_bfloat16* o2 = g_y2c + (size_t)b * MP;

    const float4* xr4 = (const float4*)xr;
    for (int i = tid; i < N / 4; i += blockDim.x)
        ((float4*)sx)[i] = xr4[i];
    __syncthreads();

    const float xmin   = g_xmin;
    const float range  = g_xmax - xmin;
    const float inv_m1 = 1.0f / (float)(M_C - 1);
    const float x0 = sx[0];
    const float xN = sx[N - 1];

    float s1 = 0.f, s2 = 0.f;

    const int m0    = tid * CH;
    const int m_end = min(m0 + CH, MP);

    if (m0 < MP) {
        // initial lower_bound for first in-range point
        int lo;
        {
            int mm = min(m0, M_C - 1);
            float t  = (mm == M_C - 1) ? 1.0f : (float)mm * inv_m1;
            float xc = __fmaf_rn(t, range, xmin);
            int a = 0, h = N;
            #pragma unroll 1
            while (a < h) {
                int mid = (a + h) >> 1;
                if (sx[mid] < xc) a = mid + 1; else h = mid;
            }
            lo = a;
        }

        uint32_t buf1[CH / 2], buf2[CH / 2];
        #pragma unroll
        for (int kk = 0; kk < CH / 2; kk++) {
            float va1 = 0.f, va2 = 0.f, vb1 = 0.f, vb2 = 0.f;
            #pragma unroll
            for (int half = 0; half < 2; half++) {
                const int m = m0 + kk * 2 + half;
                float v1 = 0.f, v2 = 0.f;
                if (m < M_C) {
                    float t  = (m == M_C - 1) ? 1.0f : (float)m * inv_m1;
                    float xc = __fmaf_rn(t, range, xmin);
                    // monotone advance: lo = lower_bound(xc)
                    #pragma unroll 1
                    while (lo < N && sx[lo] < xc) lo++;
                    if (xc >= x0 && xc <= xN) {
                        int li  = min(max(lo - 1, 0), N - 2);
                        int hiI = min(lo, N - 1);
                        float xl = sx[li], xh = sx[hiI];
                        float denom = xh - xl;
                        if (denom == 0.f) denom = 1.f;
                        float w = fminf(fmaxf((xc - xl) / (denom + 1e-9f), 0.f), 1.f);
                        float a1 = __ldg(y1r + li), b1 = __ldg(y1r + hiI);
                        float a2 = __ldg(y2r + li), b2 = __ldg(y2r + hiI);
                        v1 = __fmaf_rn(w, b1 - a1, a1);
                        v2 = __fmaf_rn(w, b2 - a2, a2);
                        s1 += v1 * v1; s2 += v2 * v2;
                    }
                }
                if (half == 0) { va1 = v1; va2 = v2; } else { vb1 = v1; vb2 = v2; }
            }
            __nv_bfloat162 p1 = __floats2bfloat162_rn(va1, vb1);
            __nv_bfloat162 p2 = __floats2bfloat162_rn(va2, vb2);
            buf1[kk] = *(uint32_t*)&p1;
            buf2[kk] = *(uint32_t*)&p2;
        }

        if (m_end - m0 == CH) {
            // 24B per thread, 8B-aligned -> 3 vector stores per array
            uint2* p1 = (uint2*)(o1 + m0);
            uint2* p2 = (uint2*)(o2 + m0);
            #pragma unroll
            for (int k = 0; k < CH / 4; k++) {
                p1[k] = make_uint2(buf1[k * 2], buf1[k * 2 + 1]);
                p2[k] = make_uint2(buf2[k * 2], buf2[k * 2 + 1]);
            }
        } else {
            // single partial thread: scalar stores
            for (int m = m0; m < m_end; m++) {
                int kk = (m - m0) >> 1, half = (m - m0) & 1;
                uint32_t w1 = buf1[kk], w2 = buf2[kk];
                o1[m] = ((__nv_bfloat16*)&w1)[half];
                o2[m] = ((__nv_bfloat16*)&w2)[half];
            }
        }
    }

    // per-row sq means
    #pragma unroll
    for (int o = 16; o > 0; o >>= 1) {
        s1 += __shfl_xor_sync(0xffffffffu, s1, o);
        s2 += __shfl_xor_sync(0xffffffffu, s2, o);
    }
    if ((tid & 31) == 0) { red1[tid >> 5] = s1; red2[tid >> 5] = s2; }
    __syncthreads();
    if (tid == 0) {
        float t1 = 0.f, t2 = 0.f;
        #pragma unroll
        for (int w = 0; w < 8; w++) { t1 += red1[w]; t2 += red2[w]; }
        g_sq1[b] = t1 * (1.0f / (float)M_C);
        g_sq2[b] = t2 * (1.0f / (float)M_C);
    }
}

// ---------------- kernel 3: bf16 tensor-core GEMM + fused loss epilogue ----
// 64x64 block tiles -> grid 256, 2 CTAs/SM (16 warps/SM) for latency hiding.
// 8 warps (4 along M x 2 along N), warp tile 16x32, BK=32, 4-stage cp.async.
#define GBM 64
#define GBN 64
#define GBK 32
#define ROW_B 80                       // bytes per smem row (32 bf16 + pad)
#define SA_STAGE (GBM * ROW_B)         // 5120 B
#define SB_STAGE (GBN * ROW_B)         // 5120 B
#define NSTAGE 4
#define SB_BASE (NSTAGE * SA_STAGE)    // 20480
#define SMEM_TOT (SB_BASE + NSTAGE * SB_STAGE)  // 40960 B

__device__ __forceinline__ void cp16(uint32_t dst, const void* src) {
    asm volatile("cp.async.cg.shared.global [%0], [%1], 16;\n"
                 :: "r"(dst), "l"(src));
}
__device__ __forceinline__ void ldsm_x4(uint32_t addr, uint32_t& r0, uint32_t& r1,
                                        uint32_t& r2, uint32_t& r3) {
    asm volatile("ldmatrix.sync.aligned.m8n8.x4.shared.b16 {%0,%1,%2,%3}, [%4];\n"
                 : "=r"(r0), "=r"(r1), "=r"(r2), "=r"(r3) : "r"(addr));
}
__device__ __forceinline__ void mma16816(float* c, const uint32_t* a, const uint32_t* b) {
    asm volatile(
        "mma.sync.aligned.m16n8k16.row.col.f32.bf16.bf16.f32 "
        "{%0,%1,%2,%3}, {%4,%5,%6,%7}, {%8,%9}, {%0,%1,%2,%3};\n"
        : "+f"(c[0]), "+f"(c[1]), "+f"(c[2]), "+f"(c[3])
        : "r"(a[0]), "r"(a[1]), "r"(a[2]), "r"(a[3]), "r"(b[0]), "r"(b[1]));
}

__global__ __launch_bounds__(256, 2) void gemm_loss_kernel(float* __restrict__ out, int B) {
    __shared__ __align__(16) unsigned char smem[SMEM_TOT];
    const uint32_t smem_u = (uint32_t)__cvta_generic_to_shared(smem);

    const int tid  = threadIdx.x;
    const int warp = tid >> 5;
    const int lane = tid & 31;

    const __nv_bfloat16* Ag = g_y1c + (size_t)blockIdx.y * GBM * MP;
    const __nv_bfloat16* Bg = g_y2c + (size_t)blockIdx.x * GBN * MP;

    const int a_row0 = tid >> 2, a_c = tid & 3;   // 64 rows x 4 k-chunks

    const int nkb = MP / GBK;    // 94

    auto load_stage = [&](int st, int kb) {
        const int k0 = kb * GBK;
        cp16(smem_u + st * SA_STAGE + a_row0 * ROW_B + a_c * 16,
             Ag + (size_t)a_row0 * MP + k0 + a_c * 8);
        cp16(smem_u + SB_BASE + st * SB_STAGE + a_row0 * ROW_B + a_c * 16,
             Bg + (size_t)a_row0 * MP + k0 + a_c * 8);
    };

    load_stage(0, 0); asm volatile("cp.async.commit_group;\n" ::);
    load_stage(1, 1); asm volatile("cp.async.commit_group;\n" ::);
    load_stage(2, 2); asm volatile("cp.async.commit_group;\n" ::);

    const int wm = (warp >> 1) * 16;   // 4 warps along M
    const int wn = (warp & 1) * 32;    // 2 warps along N
    const int lr = lane & 7, q = lane >> 3;

    const uint32_t a_addr_base = smem_u + (wm + lr + (q & 1) * 8) * ROW_B + (q >> 1) * 16;
    const uint32_t b_addr_base = smem_u + SB_BASE + (wn + lr + (q >> 1) * 8) * ROW_B + (q & 1) * 16;

    float acc[4][4];
    #pragma unroll
    for (int nf = 0; nf < 4; nf++)
        #pragma unroll
        for (int r = 0; r < 4; r++) acc[nf][r] = 0.f;

    for (int kb = 0; kb < nkb; kb++) {
        asm volatile("cp.async.wait_group 2;\n" ::);
        __syncthreads();
        if (kb + 3 < nkb) load_stage((kb + 3) % NSTAGE, kb + 3);
        asm volatile("cp.async.commit_group;\n" ::);

        const int st = kb % NSTAGE;
        const uint32_t aS = a_addr_base + st * SA_STAGE;
        const uint32_t bS = b_addr_base + st * SB_STAGE;

        #pragma unroll
        for (int s = 0; s < 2; s++) {      // two k16 sub-steps per BK=32
            uint32_t a[4], b[2][4];
            ldsm_x4(aS + s * 32, a[0], a[1], a[2], a[3]);
            #pragma unroll
            for (int p = 0; p < 2; p++)
                ldsm_x4(bS + (p * 16) * ROW_B + s * 32,
                        b[p][0], b[p][1], b[p][2], b[p][3]);
            #pragma unroll
            for (int nf = 0; nf < 4; nf++) {
                uint32_t bb[2] = { b[nf >> 1][(nf & 1) * 2],
                                   b[nf >> 1][(nf & 1) * 2 + 1] };
                mma16816(acc[nf], a, bb);
            }
        }
    }

    // fused loss epilogue
    const float inv_m = 1.0f / (float)M_C;
    const int gm = blockIdx.y * GBM + wm;
    const int gn = blockIdx.x * GBN + wn;
    #pragma unroll
    for (int h = 0; h < 2; h++) {
        const int i = gm + (lane >> 2) + h * 8;
        const float s1 = g_sq1[i];
        const float base = s1 + g_sq2[i] + EPS_B;   // reference quirk: both i-indexed
        const float scale = 2.0f / base;
        #pragma unroll
        for (int nf = 0; nf < 4; nf++) {
            const int j = gn + nf * 8 + (lane & 3) * 2;
            float c0 = acc[nf][h * 2 + 0];
            float c1 = acc[nf][h * 2 + 1];
            float d0 = fmaxf(s1 + g_sq2[j]     - 2.0f * c0 * inv_m, 0.f);
            float d1 = fmaxf(s1 + g_sq2[j + 1] - 2.0f * c1 * inv_m, 0.f);
            float2 o = { sqrtf(d0 * scale), sqrtf(d1 * scale) };
            *(float2*)(out + (size_t)i * B + j) = o;
        }
    }
}

// ---------------- launch ----------------
extern "C" void kernel_launch(void* const* d_in, const int* in_sizes, int n_in,
                              void* d_out, int out_size) {
    const float* x  = (const float*)d_in[0];
    const float* y1 = (const float*)d_in[1];
    const float* y2 = (const float*)d_in[2];
    float* out = (float*)d_out;

    // out is [B, B] -> exact integer sqrt
    int B = 1;
    while ((long long)(B + 1) * (B + 1) <= (long long)out_size) B++;
    int N = in_sizes[0] / B;

    minmax_kernel<<<1, 1024>>>(x, B, N);
    interp_kernel<<<B, 256>>>(x, y1, y2, N);
    dim3 grid(B / GBN, B / GBM);   // (16, 16)
    gemm_loss_kernel<<<grid, 256>>>(out, B);
}

// round 6
// speedup vs baseline: 1.4712x; 1.4712x over previous
#include <cuda_runtime.h>
#include <cuda_bf16.h>
#include <math.h>
#include <stdint.h>

// Problem constants (dataset-fixed shapes)
#define B_SZ   1024
#define N_SZ   8192
#define M_C    3000        // N_COMMON
#define MP     3008        // padded M (multiple of 32, zero-filled tail)
#define EPS_B  1e-8f
#define NBUCK  2048        // bucket table size (avg N/NBUCK = 4 pts/bucket)

// ---------------- scratch (no runtime allocation allowed) ----------------
__device__ __align__(16) __nv_bfloat16 g_y1c[B_SZ * MP];
__device__ __align__(16) __nv_bfloat16 g_y2c[B_SZ * MP];
__device__ float g_sq1[B_SZ];
__device__ float g_sq2[B_SZ];
__device__ float g_xmin;
__device__ float g_xmax;

// ---------------- kernel 1: batch-scalar min/max ----------------
__global__ void minmax_kernel(const float* __restrict__ x, int B, int N) {
    __shared__ float smin[32], smax[32];
    int tid = threadIdx.x;
    float mn = INFINITY, mx = -INFINITY;
    for (int b = tid; b < B; b += blockDim.x) {
        mn = fminf(mn, x[(size_t)b * N]);
        mx = fmaxf(mx, x[(size_t)b * N + (N - 1)]);
    }
    #pragma unroll
    for (int o = 16; o > 0; o >>= 1) {
        mn = fminf(mn, __shfl_xor_sync(0xffffffffu, mn, o));
        mx = fmaxf(mx, __shfl_xor_sync(0xffffffffu, mx, o));
    }
    if ((tid & 31) == 0) { smin[tid >> 5] = mn; smax[tid >> 5] = mx; }
    __syncthreads();
    if (tid < 32) {
        int nw = (blockDim.x + 31) >> 5;
        mn = (tid < nw) ? smin[tid] : INFINITY;
        mx = (tid < nw) ? smax[tid] : -INFINITY;
        #pragma unroll
        for (int o = 16; o > 0; o >>= 1) {
            mn = fminf(mn, __shfl_xor_sync(0xffffffffu, mn, o));
            mx = fmaxf(mx, __shfl_xor_sync(0xffffffffu, mx, o));
        }
        if (tid == 0) { g_xmin = mn; g_xmax = mx; }
    }
}

// ---------------- kernel 2: interpolation (bucket-accelerated searchsorted)
// One block per batch row; x row in shared. A 2048-entry bucket table maps
// value ranges -> first x-index; per query, start at the first non-empty
// bucket >= bucket(xc) (provably <= lower_bound(xc)) and scan forward ~2
// steps to the EXACT lower_bound. Same result as full binary search.
__global__ __launch_bounds__(256) void interp_kernel(
    const float* __restrict__ x,
    const float* __restrict__ y1,
    const float* __restrict__ y2,
    int N)
{
    __shared__ float sx[N_SZ];
    __shared__ int   tbl[NBUCK];
    __shared__ float red1[8], red2[8];

    const int b   = blockIdx.x;
    const int tid = threadIdx.x;

    const float* xr  = x  + (size_t)b * N;
    const float* y1r = y1 + (size_t)b * N;
    const float* y2r = y2 + (size_t)b * N;

    // coalesced vector load of the sorted x row + table init
    const float4* xr4 = (const float4*)xr;
    for (int i = tid; i < N / 4; i += blockDim.x)
        ((float4*)sx)[i] = xr4[i];
    for (int k = tid; k < NBUCK; k += blockDim.x)
        tbl[k] = N;
    __syncthreads();

    const float xmin   = g_xmin;
    const float range  = g_xmax - xmin;
    const float inv_m1 = 1.0f / (float)(M_C - 1);
    const float bscale = (float)NBUCK / range;
    const float x0 = sx[0];
    const float xN = sx[N - 1];

    // build bucket table: tbl[k] = min index whose x falls in bucket k
    for (int i = tid; i < N; i += blockDim.x) {
        int bk = (int)((sx[i] - xmin) * bscale);
        bk = min(max(bk, 0), NBUCK - 1);
        atomicMin(&tbl[bk], i);
    }
    __syncthreads();

    float s1 = 0.f, s2 = 0.f;

    for (int m = tid; m < MP; m += blockDim.x) {
        float v1 = 0.f, v2 = 0.f;
        if (m < M_C) {
            float t  = (m == M_C - 1) ? 1.0f : (float)m * inv_m1;
            float xc = __fmaf_rn(t, range, xmin);
            if (xc >= x0 && xc <= xN) {
                // start index from bucket table (first non-empty bucket >= bk)
                int bk = (int)((xc - xmin) * bscale);
                bk = min(max(bk, 0), NBUCK - 1);
                int lo = N;
                #pragma unroll 1
                for (int kk = bk; kk < NBUCK; kk++) {
                    int tv = tbl[kk];
                    if (tv < N) { lo = tv; break; }
                }
                // exact lower_bound via short forward scan
                #pragma unroll 1
                while (lo < N && sx[lo] < xc) lo++;

                int li  = min(max(lo - 1, 0), N - 2);
                int hiI = min(lo, N - 1);
                float xl = sx[li], xh = sx[hiI];
                float denom = xh - xl;
                if (denom == 0.f) denom = 1.f;
                float w = fminf(fmaxf((xc - xl) / (denom + 1e-9f), 0.f), 1.f);
                float a1 = __ldg(y1r + li), b1 = __ldg(y1r + hiI);
                float a2 = __ldg(y2r + li), b2 = __ldg(y2r + hiI);
                v1 = __fmaf_rn(w, b1 - a1, a1);
                v2 = __fmaf_rn(w, b2 - a2, a2);
            }
        }
        g_y1c[(size_t)b * MP + m] = __float2bfloat16(v1);
        g_y2c[(size_t)b * MP + m] = __float2bfloat16(v2);
        s1 += v1 * v1;
        s2 += v2 * v2;
    }

    // per-row sq means
    #pragma unroll
    for (int o = 16; o > 0; o >>= 1) {
        s1 += __shfl_xor_sync(0xffffffffu, s1, o);
        s2 += __shfl_xor_sync(0xffffffffu, s2, o);
    }
    if ((tid & 31) == 0) { red1[tid >> 5] = s1; red2[tid >> 5] = s2; }
    __syncthreads();
    if (tid == 0) {
        float t1 = 0.f, t2 = 0.f;
        #pragma unroll
        for (int w = 0; w < 8; w++) { t1 += red1[w]; t2 += red2[w]; }
        g_sq1[b] = t1 * (1.0f / (float)M_C);
        g_sq2[b] = t2 * (1.0f / (float)M_C);
    }
}

// ---------------- kernel 3: bf16 tensor-core GEMM + fused loss epilogue ----
// (measured-good R3/R4 config: 47.2us) 128x64 block tile, BK=32, 8 warps
// (4x2), warp tile 32x32, 3-stage cp.async, 80B-padded smem rows.
#define GBM 128
#define GBN 64
#define GBK 32
#define ROW_B 80
#define SA_STAGE (GBM * ROW_B)
#define SB_STAGE (GBN * ROW_B)
#define NSTAGE 3
#define SB_BASE (NSTAGE * SA_STAGE)
#define SMEM_TOT (SB_BASE + NSTAGE * SB_STAGE)

__device__ __forceinline__ void cp16(uint32_t dst, const void* src) {
    asm volatile("cp.async.cg.shared.global [%0], [%1], 16;\n"
                 :: "r"(dst), "l"(src));
}
__device__ __forceinline__ void ldsm_x4(uint32_t addr, uint32_t& r0, uint32_t& r1,
                                        uint32_t& r2, uint32_t& r3) {
    asm volatile("ldmatrix.sync.aligned.m8n8.x4.shared.b16 {%0,%1,%2,%3}, [%4];\n"
                 : "=r"(r0), "=r"(r1), "=r"(r2), "=r"(r3) : "r"(addr));
}
__device__ __forceinline__ void mma16816(float* c, const uint32_t* a, const uint32_t* b) {
    asm volatile(
        "mma.sync.aligned.m16n8k16.row.col.f32.bf16.bf16.f32 "
        "{%0,%1,%2,%3}, {%4,%5,%6,%7}, {%8,%9}, {%0,%1,%2,%3};\n"
        : "+f"(c[0]), "+f"(c[1]), "+f"(c[2]), "+f"(c[3])
        : "r"(a[0]), "r"(a[1]), "r"(a[2]), "r"(a[3]), "r"(b[0]), "r"(b[1]));
}

__global__ __launch_bounds__(256, 1) void gemm_loss_kernel(float* __restrict__ out, int B) {
    __shared__ __align__(16) unsigned char smem[SMEM_TOT];
    const uint32_t smem_u = (uint32_t)__cvta_generic_to_shared(smem);

    const int tid  = threadIdx.x;
    const int warp = tid >> 5;
    const int lane = tid & 31;

    const __nv_bfloat16* Ag = g_y1c + (size_t)blockIdx.y * GBM * MP;
    const __nv_bfloat16* Bg = g_y2c + (size_t)blockIdx.x * GBN * MP;

    const int a_row0 = tid >> 2, a_c = tid & 3;

    const int nkb = MP / GBK;    // 94

    auto load_stage = [&](int st, int kb) {
        const int k0 = kb * GBK;
        cp16(smem_u + st * SA_STAGE + a_row0 * ROW_B + a_c * 16,
             Ag + (size_t)a_row0 * MP + k0 + a_c * 8);
        cp16(smem_u + st * SA_STAGE + (a_row0 + 64) * ROW_B + a_c * 16,
             Ag + (size_t)(a_row0 + 64) * MP + k0 + a_c * 8);
        cp16(smem_u + SB_BASE + st * SB_STAGE + a_row0 * ROW_B + a_c * 16,
             Bg + (size_t)a_row0 * MP + k0 + a_c * 8);
    };

    load_stage(0, 0); asm volatile("cp.async.commit_group;\n" ::);
    load_stage(1, 1); asm volatile("cp.async.commit_group;\n" ::);

    const int wm = (warp >> 1) * 32;
    const int wn = (warp & 1) * 32;
    const int lr = lane & 7, q = lane >> 3;

    const uint32_t a_addr_base = smem_u + (wm + lr + (q & 1) * 8) * ROW_B + (q >> 1) * 16;
    const uint32_t b_addr_base = smem_u + SB_BASE + (wn + lr + (q >> 1) * 8) * ROW_B + (q & 1) * 16;

    float acc[2][4][4];
    #pragma unroll
    for (int mf = 0; mf < 2; mf++)
        #pragma unroll
        for (int nf = 0; nf < 4; nf++)
            #pragma unroll
            for (int r = 0; r < 4; r++) acc[mf][nf][r] = 0.f;

    for (int kb = 0; kb < nkb; kb++) {
        asm volatile("cp.async.wait_group 1;\n" ::);
        __syncthreads();
        if (kb + 2 < nkb) load_stage((kb + 2) % NSTAGE, kb + 2);
        asm volatile("cp.async.commit_group;\n" ::);

        const int st = kb % NSTAGE;
        const uint32_t aS = a_addr_base + st * SA_STAGE;
        const uint32_t bS = b_addr_base + st * SB_STAGE;

        #pragma unroll
        for (int s = 0; s < 2; s++) {
            uint32_t a[2][4], b[2][4];
            #pragma unroll
            for (int mf = 0; mf < 2; mf++)
                ldsm_x4(aS + (mf * 16) * ROW_B + s * 32,
                        a[mf][0], a[mf][1], a[mf][2], a[mf][3]);
            #pragma unroll
            for (int p = 0; p < 2; p++)
                ldsm_x4(bS + (p * 16) * ROW_B + s * 32,
                        b[p][0], b[p][1], b[p][2], b[p][3]);
            #pragma unroll
            for (int mf = 0; mf < 2; mf++)
                #pragma unroll
                for (int nf = 0; nf < 4; nf++) {
                    uint32_t bb[2] = { b[nf >> 1][(nf & 1) * 2],
                                       b[nf >> 1][(nf & 1) * 2 + 1] };
                    mma16816(acc[mf][nf], a[mf], bb);
                }
        }
    }

    // fused loss epilogue
    const float inv_m = 1.0f / (float)M_C;
    const int gm = blockIdx.y * GBM + wm;
    const int gn = blockIdx.x * GBN + wn;
    #pragma unroll
    for (int mf = 0; mf < 2; mf++) {
        #pragma unroll
        for (int h = 0; h < 2; h++) {
            const int i = gm + mf * 16 + (lane >> 2) + h * 8;
            const float s1 = g_sq1[i];
            const float base = s1 + g_sq2[i] + EPS_B;   // reference quirk: both i-indexed
            const float scale = 2.0f / base;
            #pragma unroll
            for (int nf = 0; nf < 4; nf++) {
                const int j = gn + nf * 8 + (lane & 3) * 2;
                float c0 = acc[mf][nf][h * 2 + 0];
                float c1 = acc[mf][nf][h * 2 + 1];
                float d0 = fmaxf(s1 + g_sq2[j]     - 2.0f * c0 * inv_m, 0.f);
                float d1 = fmaxf(s1 + g_sq2[j + 1] - 2.0f * c1 * inv_m, 0.f);
                float2 o = { sqrtf(d0 * scale), sqrtf(d1 * scale) };
                *(float2*)(out + (size_t)i * B + j) = o;
            }
        }
    }
}

// ---------------- launch ----------------
extern "C" void kernel_launch(void* const* d_in, const int* in_sizes, int n_in,
                              void* d_out, int out_size) {
    const float* x  = (const float*)d_in[0];
    const float* y1 = (const float*)d_in[1];
    const float* y2 = (const float*)d_in[2];
    float* out = (float*)d_out;

    // out is [B, B] -> exact integer sqrt
    int B = 1;
    while ((long long)(B + 1) * (B + 1) <= (long long)out_size) B++;
    int N = in_sizes[0] / B;

    minmax_kernel<<<1, 1024>>>(x, B, N);
    interp_kernel<<<B, 256>>>(x, y1, y2, N);
    dim3 grid(B / GBN, B / GBM);   // (16, 8)
    gemm_loss_kernel<<<grid, 256>>>(out, B);
}

// round 7
// speedup vs baseline: 1.8189x; 1.2364x over previous
#include <cuda_runtime.h>
#include <cuda_bf16.h>
#include <math.h>
#include <stdint.h>

// Problem constants (dataset-fixed shapes)
#define B_SZ   1024
#define N_SZ   8192        // power of two -> fixed 13-step branchless search
#define M_C    3000        // N_COMMON
#define MP     3008        // padded M (multiple of 32, zero-filled tail)
#define EPS_B  1e-8f
#define NIT    12          // ceil(MP/256) points per thread

// ---------------- scratch (no runtime allocation allowed) ----------------
__device__ __align__(16) __nv_bfloat16 g_y1c[B_SZ * MP];
__device__ __align__(16) __nv_bfloat16 g_y2c[B_SZ * MP];
__device__ float g_sq1[B_SZ];
__device__ float g_sq2[B_SZ];
__device__ float g_xmin;
__device__ float g_xmax;

// ---------------- kernel 1: batch-scalar min/max ----------------
__global__ void minmax_kernel(const float* __restrict__ x, int B, int N) {
    __shared__ float smin[32], smax[32];
    int tid = threadIdx.x;
    float mn = INFINITY, mx = -INFINITY;
    for (int b = tid; b < B; b += blockDim.x) {
        mn = fminf(mn, x[(size_t)b * N]);
        mx = fmaxf(mx, x[(size_t)b * N + (N - 1)]);
    }
    #pragma unroll
    for (int o = 16; o > 0; o >>= 1) {
        mn = fminf(mn, __shfl_xor_sync(0xffffffffu, mn, o));
        mx = fmaxf(mx, __shfl_xor_sync(0xffffffffu, mx, o));
    }
    if ((tid & 31) == 0) { smin[tid >> 5] = mn; smax[tid >> 5] = mx; }
    __syncthreads();
    if (tid < 32) {
        int nw = (blockDim.x + 31) >> 5;
        mn = (tid < nw) ? smin[tid] : INFINITY;
        mx = (tid < nw) ? smax[tid] : -INFINITY;
        #pragma unroll
        for (int o = 16; o > 0; o >>= 1) {
            mn = fminf(mn, __shfl_xor_sync(0xffffffffu, mn, o));
            mx = fmaxf(mx, __shfl_xor_sync(0xffffffffu, mx, o));
        }
        if (tid == 0) { g_xmin = mn; g_xmax = mx; }
    }
}

// ---------------- kernel 2: interpolation, search/gather decoupled --------
// One block per batch row; x row in shared. Phase A: 12 independent
// branchless 13-step lower_bound searches per thread (unrolled -> ILP).
// Phase B: all gathers issued together (MLP ~48) then combined arithmetically
// (mask multiply, no divergence). Results bitwise-identical to binary search.
__global__ __launch_bounds__(256) void interp_kernel(
    const float* __restrict__ x,
    const float* __restrict__ y1,
    const float* __restrict__ y2,
    int N)
{
    __shared__ float sx[N_SZ];
    __shared__ float red1[8], red2[8];

    const int b   = blockIdx.x;
    const int tid = threadIdx.x;

    const float* xr  = x  + (size_t)b * N;
    const float* y1r = y1 + (size_t)b * N;
    const float* y2r = y2 + (size_t)b * N;
    __nv_bfloat16* o1 = g_y1c + (size_t)b * MP;
    __nv_bfloat16* o2 = g_y2c + (size_t)b * MP;

    const float4* xr4 = (const float4*)xr;
    for (int i = tid; i < N / 4; i += blockDim.x)
        ((float4*)sx)[i] = xr4[i];
    __syncthreads();

    const float xmin   = g_xmin;
    const float range  = g_xmax - xmin;
    const float inv_m1 = 1.0f / (float)(M_C - 1);
    const float x0 = sx[0];
    const float xN = sx[N - 1];

    int   lo_a[NIT];
    float w_a[NIT];
    float msk[NIT];

    // ---- phase A: searches (independent chains -> compiler interleaves) ----
    #pragma unroll
    for (int it = 0; it < NIT; it++) {
        const int m = tid + it * 256;
        int   lo = 0;
        float w  = 0.f, mk = 0.f;
        if (m < M_C) {
            float t  = (m == M_C - 1) ? 1.0f : (float)m * inv_m1;
            float xc = __fmaf_rn(t, range, xmin);
            // branchless lower_bound over N=8192 (identical result to loop form)
            #pragma unroll
            for (int s = N_SZ / 2; s > 0; s >>= 1)
                lo += (sx[lo + s - 1] < xc) ? s : 0;
            if (xc >= x0 && xc <= xN) {
                mk = 1.f;
                int li  = min(max(lo - 1, 0), N - 2);
                int hiI = min(lo, N - 1);
                float xl = sx[li], xh = sx[hiI];
                float denom = xh - xl;
                if (denom == 0.f) denom = 1.f;
                w = fminf(fmaxf((xc - xl) / (denom + 1e-9f), 0.f), 1.f);
            }
        }
        lo_a[it] = lo;
        w_a[it]  = w;
        msk[it]  = mk;
    }

    // ---- phase B: batched gathers (all loads issued before consumption) ----
    float a1v[NIT], b1v[NIT], a2v[NIT], b2v[NIT];
    #pragma unroll
    for (int it = 0; it < NIT; it++) {
        const int lo  = lo_a[it];
        const int li  = min(max(lo - 1, 0), N - 2);
        const int hiI = min(lo, N - 1);
        a1v[it] = __ldg(y1r + li);
        b1v[it] = __ldg(y1r + hiI);
        a2v[it] = __ldg(y2r + li);
        b2v[it] = __ldg(y2r + hiI);
    }

    float s1 = 0.f, s2 = 0.f;
    #pragma unroll
    for (int it = 0; it < NIT; it++) {
        const int m = tid + it * 256;
        if (m < MP) {
            const float w = w_a[it], mk = msk[it];
            float v1 = mk * __fmaf_rn(w, b1v[it] - a1v[it], a1v[it]);
            float v2 = mk * __fmaf_rn(w, b2v[it] - a2v[it], a2v[it]);
            o1[m] = __float2bfloat16(v1);
            o2[m] = __float2bfloat16(v2);
            s1 += v1 * v1;
            s2 += v2 * v2;
        }
    }

    // per-row sq means
    #pragma unroll
    for (int o = 16; o > 0; o >>= 1) {
        s1 += __shfl_xor_sync(0xffffffffu, s1, o);
        s2 += __shfl_xor_sync(0xffffffffu, s2, o);
    }
    if ((tid & 31) == 0) { red1[tid >> 5] = s1; red2[tid >> 5] = s2; }
    __syncthreads();
    if (tid == 0) {
        float t1 = 0.f, t2 = 0.f;
        #pragma unroll
        for (int w = 0; w < 8; w++) { t1 += red1[w]; t2 += red2[w]; }
        g_sq1[b] = t1 * (1.0f / (float)M_C);
        g_sq2[b] = t2 * (1.0f / (float)M_C);
    }
}

// ---------------- kernel 3: bf16 tensor-core GEMM + fused loss epilogue ----
// 64x64 block tiles -> grid 256 (>148 SMs), 2 CTAs/SM, 16 warps/SM.
// 8 warps (4 along M x 2 along N), warp tile 16x32, BK=32, 4-stage cp.async.
#define GBM 64
#define GBN 64
#define GBK 32
#define ROW_B 80                       // bytes per smem row (32 bf16 + pad)
#define SA_STAGE (GBM * ROW_B)         // 5120 B
#define SB_STAGE (GBN * ROW_B)         // 5120 B
#define NSTAGE 4
#define SB_BASE (NSTAGE * SA_STAGE)    // 20480
#define SMEM_TOT (SB_BASE + NSTAGE * SB_STAGE)  // 40960 B

__device__ __forceinline__ void cp16(uint32_t dst, const void* src) {
    asm volatile("cp.async.cg.shared.global [%0], [%1], 16;\n"
                 :: "r"(dst), "l"(src));
}
__device__ __forceinline__ void ldsm_x4(uint32_t addr, uint32_t& r0, uint32_t& r1,
                                        uint32_t& r2, uint32_t& r3) {
    asm volatile("ldmatrix.sync.aligned.m8n8.x4.shared.b16 {%0,%1,%2,%3}, [%4];\n"
                 : "=r"(r0), "=r"(r1), "=r"(r2), "=r"(r3) : "r"(addr));
}
__device__ __forceinline__ void mma16816(float* c, const uint32_t* a, const uint32_t* b) {
    asm volatile(
        "mma.sync.aligned.m16n8k16.row.col.f32.bf16.bf16.f32 "
        "{%0,%1,%2,%3}, {%4,%5,%6,%7}, {%8,%9}, {%0,%1,%2,%3};\n"
        : "+f"(c[0]), "+f"(c[1]), "+f"(c[2]), "+f"(c[3])
        : "r"(a[0]), "r"(a[1]), "r"(a[2]), "r"(a[3]), "r"(b[0]), "r"(b[1]));
}

__global__ __launch_bounds__(256, 2) void gemm_loss_kernel(float* __restrict__ out, int B) {
    __shared__ __align__(16) unsigned char smem[SMEM_TOT];
    const uint32_t smem_u = (uint32_t)__cvta_generic_to_shared(smem);

    const int tid  = threadIdx.x;
    const int warp = tid >> 5;
    const int lane = tid & 31;

    const __nv_bfloat16* Ag = g_y1c + (size_t)blockIdx.y * GBM * MP;
    const __nv_bfloat16* Bg = g_y2c + (size_t)blockIdx.x * GBN * MP;

    const int a_row0 = tid >> 2, a_c = tid & 3;   // 64 rows x 4 k-chunks

    const int nkb = MP / GBK;    // 94

    auto load_stage = [&](int st, int kb) {
        const int k0 = kb * GBK;
        cp16(smem_u + st * SA_STAGE + a_row0 * ROW_B + a_c * 16,
             Ag + (size_t)a_row0 * MP + k0 + a_c * 8);
        cp16(smem_u + SB_BASE + st * SB_STAGE + a_row0 * ROW_B + a_c * 16,
             Bg + (size_t)a_row0 * MP + k0 + a_c * 8);
    };

    load_stage(0, 0); asm volatile("cp.async.commit_group;\n" ::);
    load_stage(1, 1); asm volatile("cp.async.commit_group;\n" ::);
    load_stage(2, 2); asm volatile("cp.async.commit_group;\n" ::);

    const int wm = (warp >> 1) * 16;   // 4 warps along M
    const int wn = (warp & 1) * 32;    // 2 warps along N
    const int lr = lane & 7, q = lane >> 3;

    const uint32_t a_addr_base = smem_u + (wm + lr + (q & 1) * 8) * ROW_B + (q >> 1) * 16;
    const uint32_t b_addr_base = smem_u + SB_BASE + (wn + lr + (q >> 1) * 8) * ROW_B + (q & 1) * 16;

    float acc[4][4];
    #pragma unroll
    for (int nf = 0; nf < 4; nf++)
        #pragma unroll
        for (int r = 0; r < 4; r++) acc[nf][r] = 0.f;

    for (int kb = 0; kb < nkb; kb++) {
        asm volatile("cp.async.wait_group 2;\n" ::);
        __syncthreads();
        if (kb + 3 < nkb) load_stage((kb + 3) % NSTAGE, kb + 3);
        asm volatile("cp.async.commit_group;\n" ::);

        const int st = kb % NSTAGE;
        const uint32_t aS = a_addr_base + st * SA_STAGE;
        const uint32_t bS = b_addr_base + st * SB_STAGE;

        #pragma unroll
        for (int s = 0; s < 2; s++) {      // two k16 sub-steps per BK=32
            uint32_t a[4], b[2][4];
            ldsm_x4(aS + s * 32, a[0], a[1], a[2], a[3]);
            #pragma unroll
            for (int p = 0; p < 2; p++)
                ldsm_x4(bS + (p * 16) * ROW_B + s * 32,
                        b[p][0], b[p][1], b[p][2], b[p][3]);
            #pragma unroll
            for (int nf = 0; nf < 4; nf++) {
                uint32_t bb[2] = { b[nf >> 1][(nf & 1) * 2],
                                   b[nf >> 1][(nf & 1) * 2 + 1] };
                mma16816(acc[nf], a, bb);
            }
        }
    }

    // fused loss epilogue
    const float inv_m = 1.0f / (float)M_C;
    const int gm = blockIdx.y * GBM + wm;
    const int gn = blockIdx.x * GBN + wn;
    #pragma unroll
    for (int h = 0; h < 2; h++) {
        const int i = gm + (lane >> 2) + h * 8;
        const float s1 = g_sq1[i];
        const float base = s1 + g_sq2[i] + EPS_B;   // reference quirk: both i-indexed
        const float scale = 2.0f / base;
        #pragma unroll
        for (int nf = 0; nf < 4; nf++) {
            const int j = gn + nf * 8 + (lane & 3) * 2;
            float c0 = acc[nf][h * 2 + 0];
            float c1 = acc[nf][h * 2 + 1];
            float d0 = fmaxf(s1 + g_sq2[j]     - 2.0f * c0 * inv_m, 0.f);
            float d1 = fmaxf(s1 + g_sq2[j + 1] - 2.0f * c1 * inv_m, 0.f);
            float2 o = { sqrtf(d0 * scale), sqrtf(d1 * scale) };
            *(float2*)(out + (size_t)i * B + j) = o;
        }
    }
}

// ---------------- launch ----------------
extern "C" void kernel_launch(void* const* d_in, const int* in_sizes, int n_in,
                              void* d_out, int out_size) {
    const float* x  = (const float*)d_in[0];
    const float* y1 = (const float*)d_in[1];
    const float* y2 = (const float*)d_in[2];
    float* out = (float*)d_out;

    // out is [B, B] -> exact integer sqrt
    int B = 1;
    while ((long long)(B + 1) * (B + 1) <= (long long)out_size) B++;
    int N = in_sizes[0] / B;

    minmax_kernel<<<1, 1024>>>(x, B, N);
    interp_kernel<<<B, 256>>>(x, y1, y2, N);
    dim3 grid(B / GBN, B / GBM);   // (16, 16)
    gemm_loss_kernel<<<grid, 256>>>(out, B);
}